// round 1
// baseline (speedup 1.0000x reference)
#include <cuda_runtime.h>
#include <cstdint>

#define NA 100000
#define NB 100000
#define NE 1600000
#define BF 128
#define AF 128

// Scratch for a_support = b_input @ a_weight : [NB, AF] fp32 = 51.2 MB
__device__ float g_support[(size_t)NB * AF];

// ---------------------------------------------------------------------------
// Kernel 1: dense GEMM  g_support[NB,128] = B[NB,128] @ W[128,128]
// Block: 256 threads handles 16 rows. W tiled in smem as two 64x128 chunks.
// Each thread: 1 row x 8 cols register tile.
// ---------------------------------------------------------------------------
__global__ __launch_bounds__(256) void gemm_kernel(const float* __restrict__ B,
                                                   const float* __restrict__ W) {
    __shared__ float Ws[64][128];   // 32 KB
    __shared__ float Bs[16][128];   // 8 KB

    const int tid = threadIdx.x;
    const int tx  = tid & 15;       // col group: cols [tx*8, tx*8+8)
    const int ty  = tid >> 4;       // row within block: 0..15
    const int row0 = blockIdx.x * 16;

    // Load 16 B rows: 2048 floats = 512 float4, 256 threads -> 2 each
    for (int i = tid; i < 512; i += 256) {
        int r = i >> 5, c4 = i & 31;
        ((float4*)&Bs[r][0])[c4] =
            ((const float4*)(B + (size_t)(row0 + r) * BF))[c4];
    }

    float acc[8];
    #pragma unroll
    for (int j = 0; j < 8; j++) acc[j] = 0.0f;

    for (int kt = 0; kt < 2; kt++) {
        __syncthreads();
        // Load W rows [kt*64, kt*64+64): 8192 floats = 2048 float4 -> 8 each
        for (int i = tid; i < 2048; i += 256) {
            int r = i >> 5, c4 = i & 31;
            ((float4*)&Ws[r][0])[c4] =
                ((const float4*)(W + (size_t)(kt * 64 + r) * AF))[c4];
        }
        __syncthreads();

        #pragma unroll 16
        for (int k = 0; k < 64; k++) {
            float b = Bs[ty][kt * 64 + k];
            float4 w0 = ((const float4*)&Ws[k][0])[tx * 2];
            float4 w1 = ((const float4*)&Ws[k][0])[tx * 2 + 1];
            acc[0] += b * w0.x; acc[1] += b * w0.y;
            acc[2] += b * w0.z; acc[3] += b * w0.w;
            acc[4] += b * w1.x; acc[5] += b * w1.y;
            acc[6] += b * w1.z; acc[7] += b * w1.w;
        }
    }

    float* outp = g_support + (size_t)(row0 + ty) * AF + tx * 8;
    ((float4*)outp)[0] = make_float4(acc[0], acc[1], acc[2], acc[3]);
    ((float4*)outp)[1] = make_float4(acc[4], acc[5], acc[6], acc[7]);
}

// ---------------------------------------------------------------------------
// Kernel 2: out[i,:] = bias  (also clears the 0xAA poison)
// ---------------------------------------------------------------------------
__global__ __launch_bounds__(256) void init_kernel(float* __restrict__ out,
                                                   const float* __restrict__ bias) {
    int idx = blockIdx.x * blockDim.x + threadIdx.x;  // float4 index
    const int total = (NA * AF) / 4;                   // 3.2M
    if (idx < total) {
        float4 b = ((const float4*)bias)[idx & 31];    // (idx*4) % 128 -> float4 idx%32
        ((float4*)out)[idx] = b;
    }
}

// ---------------------------------------------------------------------------
// Kernel 3: COO scatter. One warp handles 4 edges. Each lane moves a float4
// (16B) of the 512B row. Gather from g_support (L2-resident), scale, and
// red.global.add.v4.f32 into out[row].
// ---------------------------------------------------------------------------
#define EDGES_PER_WARP 4

__global__ __launch_bounds__(256) void scatter_kernel(const int*   __restrict__ rows,
                                                      const int*   __restrict__ cols,
                                                      const float* __restrict__ vals,
                                                      float*       __restrict__ out) {
    const int warp = (blockIdx.x * blockDim.x + threadIdx.x) >> 5;
    const int lane = threadIdx.x & 31;
    const int e0 = warp * EDGES_PER_WARP;
    if (e0 >= NE) return;

    int    r[EDGES_PER_WARP];
    int    c[EDGES_PER_WARP];
    float  v[EDGES_PER_WARP];
    float4 g[EDGES_PER_WARP];

    // Front-batch the gathers for MLP
    #pragma unroll
    for (int i = 0; i < EDGES_PER_WARP; i++) {
        int e = e0 + i;
        r[i] = __ldg(rows + e);
        c[i] = __ldg(cols + e);
        v[i] = __ldg(vals + e);
    }
    #pragma unroll
    for (int i = 0; i < EDGES_PER_WARP; i++) {
        g[i] = __ldg((const float4*)(g_support + (size_t)c[i] * AF) + lane);
    }

    #pragma unroll
    for (int i = 0; i < EDGES_PER_WARP; i++) {
        float* dst = out + (size_t)r[i] * AF + lane * 4;
        asm volatile("red.global.add.v4.f32 [%0], {%1, %2, %3, %4};"
                     :: "l"(dst),
                        "f"(g[i].x * v[i]), "f"(g[i].y * v[i]),
                        "f"(g[i].z * v[i]), "f"(g[i].w * v[i])
                     : "memory");
    }
}

// ---------------------------------------------------------------------------
// Launch
// inputs (metadata order): b_input[NB*BF], edge_rows[NE], edge_cols[NE],
//                          edge_vals[NE], a_weight[BF*AF], a_bias[AF]
// output: [NA, AF] float32
// ---------------------------------------------------------------------------
extern "C" void kernel_launch(void* const* d_in, const int* in_sizes, int n_in,
                              void* d_out, int out_size) {
    const float* b_input   = (const float*)d_in[0];
    const int*   edge_rows = (const int*)  d_in[1];
    const int*   edge_cols = (const int*)  d_in[2];
    const float* edge_vals = (const float*)d_in[3];
    const float* a_weight  = (const float*)d_in[4];
    const float* a_bias    = (const float*)d_in[5];
    float*       out       = (float*)d_out;

    // 1) a_support = b_input @ a_weight
    gemm_kernel<<<NB / 16, 256>>>(b_input, a_weight);

    // 2) out = bias (broadcast)
    init_kernel<<<(NA * AF / 4 + 255) / 256, 256>>>(out, a_bias);

    // 3) scatter-add edges
    const int warps_needed  = (NE + EDGES_PER_WARP - 1) / EDGES_PER_WARP;  // 400000
    const int warps_per_blk = 256 / 32;                                    // 8
    const int blocks        = (warps_needed + warps_per_blk - 1) / warps_per_blk;
    scatter_kernel<<<blocks, 256>>>(edge_rows, edge_cols, edge_vals, out);
}

// round 2
// speedup vs baseline: 2.1364x; 2.1364x over previous
#include <cuda_runtime.h>
#include <cstdint>

#define NA 100000
#define NB 100000
#define NE 1600000
#define BF 128
#define AF 128

// Scratch for a_support = b_input @ a_weight : [NB, AF] fp32 = 51.2 MB
__device__ float g_support[(size_t)NB * AF];

// ---------------------------------------------------------------------------
// Kernel 1: dense GEMM  g_support[NB,128] = B[NB,128] @ W[128,128]
// Block: 256 threads, tile 128 rows x 128 cols, K-tile 32.
// Each thread: 8x8 register tile -> 4 LDS.128 per k for 64 FFMA.
// ---------------------------------------------------------------------------
#define TILE_M 128
#define KT 32

__global__ __launch_bounds__(256, 2) void gemm_kernel(const float* __restrict__ B,
                                                      const float* __restrict__ W) {
    __shared__ float BsT[KT][TILE_M];   // [k][row], 16 KB
    __shared__ float Ws [KT][128];      // [k][col], 16 KB

    const int tid = threadIdx.x;
    const int tx  = tid & 15;           // col group: cols [tx*8, tx*8+8)
    const int ty  = tid >> 4;           // row group: rows [ty*8, ty*8+8)
    const int row0 = blockIdx.x * TILE_M;

    float acc[8][8];
    #pragma unroll
    for (int i = 0; i < 8; i++)
        #pragma unroll
        for (int j = 0; j < 8; j++) acc[i][j] = 0.0f;

    for (int kt = 0; kt < BF; kt += KT) {
        // ---- Load B tile (128 rows x 32 k), transposed into BsT[k][row].
        // Mapping: r = tid&127 (warp covers 32 consecutive rows -> conflict-free STS),
        // kq = (tid>>7)*16 (two k-halves).
        {
            const int r  = tid & 127;
            const int kq = (tid >> 7) * 16;
            const int gr = min(row0 + r, NB - 1);   // clamp for last partial tile
            const float4* src = (const float4*)(B + (size_t)gr * BF + kt + kq);
            #pragma unroll
            for (int q = 0; q < 4; q++) {
                float4 v = src[q];
                int k = kq + q * 4;
                BsT[k + 0][r] = v.x;
                BsT[k + 1][r] = v.y;
                BsT[k + 2][r] = v.z;
                BsT[k + 3][r] = v.w;
            }
        }
        // ---- Load W tile (32 k x 128 cols): 1024 float4, 4 per thread.
        {
            #pragma unroll
            for (int q = 0; q < 4; q++) {
                int idx = tid + q * 256;       // 0..1023
                int kk  = idx >> 5;            // 0..31
                int cc  = idx & 31;            // float4 col index
                ((float4*)&Ws[kk][0])[cc] =
                    ((const float4*)(W + (size_t)(kt + kk) * AF))[cc];
            }
        }
        __syncthreads();

        #pragma unroll
        for (int k = 0; k < KT; k++) {
            float4 b0 = ((const float4*)&BsT[k][0])[ty * 2];
            float4 b1 = ((const float4*)&BsT[k][0])[ty * 2 + 1];
            float4 w0 = ((const float4*)&Ws[k][0])[tx * 2];
            float4 w1 = ((const float4*)&Ws[k][0])[tx * 2 + 1];
            float bb[8] = {b0.x, b0.y, b0.z, b0.w, b1.x, b1.y, b1.z, b1.w};
            float ww[8] = {w0.x, w0.y, w0.z, w0.w, w1.x, w1.y, w1.z, w1.w};
            #pragma unroll
            for (int i = 0; i < 8; i++)
                #pragma unroll
                for (int j = 0; j < 8; j++)
                    acc[i][j] += bb[i] * ww[j];
        }
        __syncthreads();
    }

    // ---- Store 8x8 tile
    #pragma unroll
    for (int i = 0; i < 8; i++) {
        int gr = row0 + ty * 8 + i;
        if (gr < NB) {
            float4* dst = (float4*)(g_support + (size_t)gr * AF + tx * 8);
            dst[0] = make_float4(acc[i][0], acc[i][1], acc[i][2], acc[i][3]);
            dst[1] = make_float4(acc[i][4], acc[i][5], acc[i][6], acc[i][7]);
        }
    }
}

// ---------------------------------------------------------------------------
// Kernel 2: out[i,:] = bias  (also clears the 0xAA poison)
// ---------------------------------------------------------------------------
__global__ __launch_bounds__(256) void init_kernel(float* __restrict__ out,
                                                   const float* __restrict__ bias) {
    int idx = blockIdx.x * blockDim.x + threadIdx.x;  // float4 index
    const int total = (NA * AF) / 4;                   // 3.2M
    if (idx < total) {
        float4 b = ((const float4*)bias)[idx & 31];    // 128 floats/row = 32 float4
        ((float4*)out)[idx] = b;
    }
}

// ---------------------------------------------------------------------------
// Kernel 3: COO scatter. One warp handles 4 edges. Each lane moves a float4
// (16B) of the 512B row. Gather from g_support (L2-resident), scale, and
// red.global.add.v4.f32 into out[row].
// ---------------------------------------------------------------------------
#define EDGES_PER_WARP 4

__global__ __launch_bounds__(256) void scatter_kernel(const int*   __restrict__ rows,
                                                      const int*   __restrict__ cols,
                                                      const float* __restrict__ vals,
                                                      float*       __restrict__ out) {
    const int warp = (blockIdx.x * blockDim.x + threadIdx.x) >> 5;
    const int lane = threadIdx.x & 31;
    const int e0 = warp * EDGES_PER_WARP;
    if (e0 >= NE) return;

    int    r[EDGES_PER_WARP];
    int    c[EDGES_PER_WARP];
    float  v[EDGES_PER_WARP];
    float4 g[EDGES_PER_WARP];

    #pragma unroll
    for (int i = 0; i < EDGES_PER_WARP; i++) {
        int e = e0 + i;
        r[i] = __ldg(rows + e);
        c[i] = __ldg(cols + e);
        v[i] = __ldg(vals + e);
    }
    #pragma unroll
    for (int i = 0; i < EDGES_PER_WARP; i++) {
        g[i] = __ldg((const float4*)(g_support + (size_t)c[i] * AF) + lane);
    }

    #pragma unroll
    for (int i = 0; i < EDGES_PER_WARP; i++) {
        float* dst = out + (size_t)r[i] * AF + lane * 4;
        asm volatile("red.global.add.v4.f32 [%0], {%1, %2, %3, %4};"
                     :: "l"(dst),
                        "f"(g[i].x * v[i]), "f"(g[i].y * v[i]),
                        "f"(g[i].z * v[i]), "f"(g[i].w * v[i])
                     : "memory");
    }
}

// ---------------------------------------------------------------------------
// Launch
// inputs: b_input[NB*BF], edge_rows[NE], edge_cols[NE], edge_vals[NE],
//         a_weight[BF*AF], a_bias[AF];  output: [NA, AF] float32
// ---------------------------------------------------------------------------
extern "C" void kernel_launch(void* const* d_in, const int* in_sizes, int n_in,
                              void* d_out, int out_size) {
    const float* b_input   = (const float*)d_in[0];
    const int*   edge_rows = (const int*)  d_in[1];
    const int*   edge_cols = (const int*)  d_in[2];
    const float* edge_vals = (const float*)d_in[3];
    const float* a_weight  = (const float*)d_in[4];
    const float* a_bias    = (const float*)d_in[5];
    float*       out       = (float*)d_out;

    // 1) a_support = b_input @ a_weight
    gemm_kernel<<<(NB + TILE_M - 1) / TILE_M, 256>>>(b_input, a_weight);

    // 2) out = bias (broadcast)
    init_kernel<<<(NA * AF / 4 + 255) / 256, 256>>>(out, a_bias);

    // 3) scatter-add edges
    const int warps_needed  = (NE + EDGES_PER_WARP - 1) / EDGES_PER_WARP;  // 400000
    const int warps_per_blk = 256 / 32;
    const int blocks        = (warps_needed + warps_per_blk - 1) / warps_per_blk;
    scatter_kernel<<<blocks, 256>>>(edge_rows, edge_cols, edge_vals, out);
}

// round 4
// speedup vs baseline: 2.4912x; 1.1661x over previous
#include <cuda_runtime.h>
#include <cstdint>

#define NA 100000
#define NB 100000
#define NE 1600000
#define BF 128
#define AF 128

// ---------------------------------------------------------------------------
// Device scratch (allocation-free rule: device globals)
// ---------------------------------------------------------------------------
__device__ float g_support[(size_t)NB * AF];   // 51.2 MB  a_support
__device__ int   g_count[NA];                  // per-row edge counts / fill cursor
__device__ int   g_excl[NA];                   // block-local exclusive scan
__device__ int   g_start[NA + 1];              // CSR row starts
__device__ int   g_bsum[256];                  // per-scan-block sums
__device__ int   g_bscan[256];                 // scanned block sums
__device__ int   g_ecol[NE];                   // CSR-ordered cols
__device__ float g_eval[NE];                   // CSR-ordered vals

#define SCAN_BS 512
#define SCAN_NBLK ((NA + SCAN_BS - 1) / SCAN_BS)   // 196

// ---------------------------------------------------------------------------
// Kernel 1: dense GEMM  g_support[NB,128] = B[NB,128] @ W[128,128]
// 256 threads, 128x128 tile, 8x8 per-thread register tile.
// ---------------------------------------------------------------------------
#define TILE_M 128
#define KT 32

__global__ __launch_bounds__(256, 2) void gemm_kernel(const float* __restrict__ B,
                                                      const float* __restrict__ W) {
    __shared__ float BsT[KT][TILE_M];   // [k][row]
    __shared__ float Ws [KT][128];      // [k][col]

    const int tid = threadIdx.x;
    const int tx  = tid & 15;
    const int ty  = tid >> 4;
    const int row0 = blockIdx.x * TILE_M;

    float acc[8][8];
    #pragma unroll
    for (int i = 0; i < 8; i++)
        #pragma unroll
        for (int j = 0; j < 8; j++) acc[i][j] = 0.0f;

    for (int kt = 0; kt < BF; kt += KT) {
        {
            const int r  = tid & 127;
            const int kq = (tid >> 7) * 16;
            const int gr = min(row0 + r, NB - 1);
            const float4* src = (const float4*)(B + (size_t)gr * BF + kt + kq);
            #pragma unroll
            for (int q = 0; q < 4; q++) {
                float4 v = src[q];
                int k = kq + q * 4;
                BsT[k + 0][r] = v.x;
                BsT[k + 1][r] = v.y;
                BsT[k + 2][r] = v.z;
                BsT[k + 3][r] = v.w;
            }
        }
        {
            #pragma unroll
            for (int q = 0; q < 4; q++) {
                int idx = tid + q * 256;
                int kk  = idx >> 5;
                int cc  = idx & 31;
                ((float4*)&Ws[kk][0])[cc] =
                    ((const float4*)(W + (size_t)(kt + kk) * AF))[cc];
            }
        }
        __syncthreads();

        #pragma unroll
        for (int k = 0; k < KT; k++) {
            float4 b0 = ((const float4*)&BsT[k][0])[ty * 2];
            float4 b1 = ((const float4*)&BsT[k][0])[ty * 2 + 1];
            float4 w0 = ((const float4*)&Ws[k][0])[tx * 2];
            float4 w1 = ((const float4*)&Ws[k][0])[tx * 2 + 1];
            float bb[8] = {b0.x, b0.y, b0.z, b0.w, b1.x, b1.y, b1.z, b1.w};
            float ww[8] = {w0.x, w0.y, w0.z, w0.w, w1.x, w1.y, w1.z, w1.w};
            #pragma unroll
            for (int i = 0; i < 8; i++)
                #pragma unroll
                for (int j = 0; j < 8; j++)
                    acc[i][j] += bb[i] * ww[j];
        }
        __syncthreads();
    }

    #pragma unroll
    for (int i = 0; i < 8; i++) {
        int gr = row0 + ty * 8 + i;
        if (gr < NB) {
            float4* dst = (float4*)(g_support + (size_t)gr * AF + tx * 8);
            dst[0] = make_float4(acc[i][0], acc[i][1], acc[i][2], acc[i][3]);
            dst[1] = make_float4(acc[i][4], acc[i][5], acc[i][6], acc[i][7]);
        }
    }
}

// ---------------------------------------------------------------------------
// CSR build
// ---------------------------------------------------------------------------
__global__ __launch_bounds__(256) void zero_counts_kernel() {
    int i = blockIdx.x * blockDim.x + threadIdx.x;
    if (i < NA) g_count[i] = 0;
}

__global__ __launch_bounds__(256) void hist_kernel(const int* __restrict__ rows) {
    int e = blockIdx.x * blockDim.x + threadIdx.x;
    if (e < NE) atomicAdd(&g_count[rows[e]], 1);
}

// Block-level inclusive scan of 512 counts; exclusive part -> g_excl, sum -> g_bsum
__global__ __launch_bounds__(SCAN_BS) void scan1_kernel() {
    __shared__ int sdata[SCAN_BS];
    const int t   = threadIdx.x;
    const int idx = blockIdx.x * SCAN_BS + t;
    int x = (idx < NA) ? g_count[idx] : 0;
    sdata[t] = x;
    __syncthreads();
    #pragma unroll
    for (int off = 1; off < SCAN_BS; off <<= 1) {
        int y = (t >= off) ? sdata[t - off] : 0;
        __syncthreads();
        sdata[t] += y;
        __syncthreads();
    }
    if (idx < NA) g_excl[idx] = sdata[t] - x;
    if (t == SCAN_BS - 1) g_bsum[blockIdx.x] = sdata[t];
}

// Single block: exclusive scan of the block sums (serial, tiny)
__global__ __launch_bounds__(256) void scan2_kernel() {
    __shared__ int s[SCAN_NBLK];
    int t = threadIdx.x;
    if (t < SCAN_NBLK) s[t] = g_bsum[t];
    __syncthreads();
    if (t == 0) {
        int run = 0;
        for (int i = 0; i < SCAN_NBLK; i++) {
            int v = s[i];
            s[i] = run;
            run += v;
        }
    }
    __syncthreads();
    if (t < SCAN_NBLK) g_bscan[t] = s[t];
}

__global__ __launch_bounds__(256) void scan3_kernel() {
    int i = blockIdx.x * blockDim.x + threadIdx.x;
    if (i < NA) g_start[i] = g_excl[i] + g_bscan[i / SCAN_BS];
    if (i == 0) g_start[NA] = NE;
}

// Place edges into CSR buckets. atomicSub drains g_count back to 0.
__global__ __launch_bounds__(256) void place_kernel(const int*   __restrict__ rows,
                                                    const int*   __restrict__ cols,
                                                    const float* __restrict__ vals) {
    int e = blockIdx.x * blockDim.x + threadIdx.x;
    if (e >= NE) return;
    int row = rows[e];
    int old = atomicSub(&g_count[row], 1);       // old in [1..cnt]
    int pos = g_start[row] + old - 1;
    g_ecol[pos] = cols[e];
    g_eval[pos] = vals[e];
}

// ---------------------------------------------------------------------------
// SpMM + bias: one warp per output row. Each out row written exactly once
// (clears the 0xAA poison, no init kernel, no atomics on out).
// ---------------------------------------------------------------------------
__global__ __launch_bounds__(256) void spmm_kernel(const float* __restrict__ bias,
                                                   float*       __restrict__ out) {
    const int warp = (blockIdx.x * blockDim.x + threadIdx.x) >> 5;
    const int lane = threadIdx.x & 31;
    if (warp >= NA) return;

    const int s    = g_start[warp];
    const int eend = g_start[warp + 1];

    float4 acc = ((const float4*)bias)[lane];

    int e = s;
    for (; e + 4 <= eend; e += 4) {
        int   c0 = g_ecol[e],     c1 = g_ecol[e + 1];
        int   c2 = g_ecol[e + 2], c3 = g_ecol[e + 3];
        float v0 = g_eval[e],     v1 = g_eval[e + 1];
        float v2 = g_eval[e + 2], v3 = g_eval[e + 3];
        float4 x0 = __ldg((const float4*)(g_support + (size_t)c0 * AF) + lane);
        float4 x1 = __ldg((const float4*)(g_support + (size_t)c1 * AF) + lane);
        float4 x2 = __ldg((const float4*)(g_support + (size_t)c2 * AF) + lane);
        float4 x3 = __ldg((const float4*)(g_support + (size_t)c3 * AF) + lane);
        acc.x += v0 * x0.x; acc.y += v0 * x0.y; acc.z += v0 * x0.z; acc.w += v0 * x0.w;
        acc.x += v1 * x1.x; acc.y += v1 * x1.y; acc.z += v1 * x1.z; acc.w += v1 * x1.w;
        acc.x += v2 * x2.x; acc.y += v2 * x2.y; acc.z += v2 * x2.z; acc.w += v2 * x2.w;
        acc.x += v3 * x3.x; acc.y += v3 * x3.y; acc.z += v3 * x3.z; acc.w += v3 * x3.w;
    }
    for (; e < eend; e++) {
        int   c = g_ecol[e];
        float v = g_eval[e];
        float4 x = __ldg((const float4*)(g_support + (size_t)c * AF) + lane);
        acc.x += v * x.x; acc.y += v * x.y; acc.z += v * x.z; acc.w += v * x.w;
    }

    ((float4*)(out + (size_t)warp * AF))[lane] = acc;
}

// ---------------------------------------------------------------------------
// Launch
// inputs: b_input[NB*BF], edge_rows[NE], edge_cols[NE], edge_vals[NE],
//         a_weight[BF*AF], a_bias[AF];  output: [NA, AF] float32
// ---------------------------------------------------------------------------
extern "C" void kernel_launch(void* const* d_in, const int* in_sizes, int n_in,
                              void* d_out, int out_size) {
    const float* b_input   = (const float*)d_in[0];
    const int*   edge_rows = (const int*)  d_in[1];
    const int*   edge_cols = (const int*)  d_in[2];
    const float* edge_vals = (const float*)d_in[3];
    const float* a_weight  = (const float*)d_in[4];
    const float* a_bias    = (const float*)d_in[5];
    float*       out       = (float*)d_out;

    // 1) a_support = b_input @ a_weight
    gemm_kernel<<<(NB + TILE_M - 1) / TILE_M, 256>>>(b_input, a_weight);

    // 2) CSR build from COO (independent of GEMM result)
    zero_counts_kernel<<<(NA + 255) / 256, 256>>>();
    hist_kernel<<<(NE + 255) / 256, 256>>>(edge_rows);
    scan1_kernel<<<SCAN_NBLK, SCAN_BS>>>();
    scan2_kernel<<<1, 256>>>();
    scan3_kernel<<<(NA + 255) / 256, 256>>>();
    place_kernel<<<(NE + 255) / 256, 256>>>(edge_rows, edge_cols, edge_vals);

    // 3) SpMM + bias, one warp per row, single STG per out row
    spmm_kernel<<<(NA * 32 + 255) / 256, 256>>>(a_bias, out);
}